// round 8
// baseline (speedup 1.0000x reference)
#include <cuda_runtime.h>
#include <cuda_bf16.h>

// BuzzLoss: B=8192 rows, T=1024 cols.
// ONE WARP PER ROW, autonomous. Lane l owns elements {j*128 + 4l + e}.
// Phase 1 (memory): 16 independent coalesced LDG.128; each segment j is
//   reduced ON ARRIVAL to 3 scalars:
//     p[j]     = prod of (1-c) over the 4 elements
//     s1loc[j] = sum local_buzz * a      (local_buzz uses prefix within the 4)
//     s2loc[j] = sum local_buzz
//   c/a die immediately -> no reloads, all DRAM traffic in one high-MLP burst.
// Phase 2 (registers only): 8 interleaved warp product-scans on p[j],
//   16 independent total/exclusive shfls, serial 8-mul R chain:
//     s1 = sum_j (R_j * excl_j) * s1loc[j]   (same for s2)
// Warp reduce -> smem accumulate -> 1 global atomic per CTA.

#define FULL_MASK 0xFFFFFFFFu
#define ROWS_PER_CTA 8

__global__ void buzz_zero_kernel(float* out) {
    out[0] = 0.0f;
}

__global__ __launch_bounds__(256)
void buzz_loss_kernel(const float* __restrict__ conf,
                      const float* __restrict__ acc,
                      float* __restrict__ out,
                      float negInvB) {
    const int tid  = threadIdx.x;
    const int lane = tid & 31;
    const int wid  = tid >> 5;
    const size_t row = (size_t)blockIdx.x * ROWS_PER_CTA + wid;

    __shared__ float s_total;
    if (tid == 0) s_total = 0.0f;
    __syncthreads();

    const float4* c4 = reinterpret_cast<const float4*>(conf + row * 1024) + lane;
    const float4* a4 = reinterpret_cast<const float4*>(acc  + row * 1024) + lane;

    // ---- Phase 1: load + immediate per-segment reduction ----
    float p[8], s1loc[8], s2loc[8];
    float lastA = 0.0f;

    #pragma unroll
    for (int j = 0; j < 8; j++) {
        const float4 c = c4[j * 32];
        const float4 a = a4[j * 32];

        const float q0 = 1.0f - c.x;
        const float q1 = 1.0f - c.y;
        const float q2 = 1.0f - c.z;
        const float q3 = 1.0f - c.w;

        const float lb0 = c.x;
        const float lb1 = c.y * q0;
        const float lb2 = c.z * (q0 * q1);
        const float lb3 = c.w * (q0 * q1 * q2);

        p[j] = (q0 * q1) * (q2 * q3);
        s1loc[j] = fmaf(lb0, a.x, fmaf(lb1, a.y, fmaf(lb2, a.z, lb3 * a.w)));
        s2loc[j] = (lb0 + lb1) + (lb2 + lb3);

        if (j == 7) lastA = a.w;           // lane 31 -> acc[row, 1023]
    }

    // ---- Phase 2: pure register/shfl math ----
    // 8 interleaved warp inclusive product-scans on p[j]
    #pragma unroll
    for (int d = 1; d < 32; d <<= 1) {
        #pragma unroll
        for (int j = 0; j < 8; j++) {
            float v = __shfl_up_sync(FULL_MASK, p[j], d);
            if (lane >= d) p[j] *= v;
        }
    }

    // Per-segment totals + lane-exclusive prefixes (16 independent shfls)
    float tot[8], E[8];
    #pragma unroll
    for (int j = 0; j < 8; j++) {
        tot[j] = __shfl_sync(FULL_MASK, p[j], 31);
        E[j]   = __shfl_up_sync(FULL_MASK, p[j], 1);
        if (lane == 0) E[j] = 1.0f;
    }

    // Serial cross-segment chain: only 8 FMULs deep
    float R = 1.0f, s1 = 0.0f, s2 = 0.0f;
    #pragma unroll
    for (int j = 0; j < 8; j++) {
        const float Ej = E[j] * R;
        s1 = fmaf(Ej, s1loc[j], s1);
        s2 = fmaf(Ej, s2loc[j], s2);
        R *= tot[j];
    }

    // Warp reduce
    #pragma unroll
    for (int d = 16; d >= 1; d >>= 1) {
        s1 += __shfl_down_sync(FULL_MASK, s1, d);
        s2 += __shfl_down_sync(FULL_MASK, s2, d);
    }
    const float accLast = __shfl_sync(FULL_MASK, lastA, 31);

    if (lane == 0) {
        const float score = s1 + (1.0f - s2) * accLast;
        atomicAdd(&s_total, score);
    }

    __syncthreads();
    if (tid == 0) {
        atomicAdd(out, s_total * negInvB);
    }
}

extern "C" void kernel_launch(void* const* d_in, const int* in_sizes, int n_in,
                              void* d_out, int out_size) {
    const float* conf = (const float*)d_in[0];
    const float* acc  = (const float*)d_in[1];
    float* out = (float*)d_out;

    const int total = in_sizes[0];
    const int T = 1024;
    const int B = total / T;

    buzz_zero_kernel<<<1, 1>>>(out);
    buzz_loss_kernel<<<B / ROWS_PER_CTA, 256>>>(conf, acc, out,
                                                -1.0f / (float)B);
}